// round 16
// baseline (speedup 1.0000x reference)
#include <cuda_runtime.h>
#include <cuda_fp16.h>
#include <math.h>
#include <stdint.h>

// Problem constants
#define BATCH 2
#define SEQ   2048
#define EMB   2048
#define HEADS 16
#define HDIM  128

// Scratch buffers (allocation-free rule: __device__ globals)
__device__ __half g_acth[BATCH * SEQ * EMB];  // fp16 activations
__device__ __half g_atth[BATCH * SEQ * EMB];  // fp16 attention output
__device__ __half g_qh[BATCH * SEQ * EMB];    // fp16 rotated+scaled Q
__device__ __half g_kh[BATCH * SEQ * EMB];    // fp16 rotated K
__device__ __half g_vh[BATCH * SEQ * EMB];    // fp16 V (row-major)
__device__ __half g_wqh[EMB * EMB];
__device__ __half g_wkh[EMB * EMB];
__device__ __half g_wvh[EMB * EMB];
__device__ __half g_woh[EMB * EMB];

// ---------------------------------------------------------------------------
// helpers
// ---------------------------------------------------------------------------
__device__ __forceinline__ uint32_t smem_u32(const void* p) {
    uint32_t a;
    asm("{ .reg .u64 t; cvta.to.shared.u64 t, %1; cvt.u32.u64 %0, t; }"
        : "=r"(a) : "l"(p));
    return a;
}

__device__ __forceinline__ float ex2(float x) {
    float r;
    asm("ex2.approx.ftz.f32 %0, %1;" : "=f"(r) : "f"(x));
    return r;
}

__device__ __forceinline__ uint32_t h2u(__half2 h) {
    return *reinterpret_cast<uint32_t*>(&h);
}

#define CP_ASYNC16(saddr, gaddr) \
    asm volatile("cp.async.ca.shared.global [%0], [%1], 16;" \
                 :: "r"(saddr), "l"(gaddr) : "memory")
#define CP_ASYNC16_CG(saddr, gaddr) \
    asm volatile("cp.async.cg.shared.global [%0], [%1], 16;" \
                 :: "r"(saddr), "l"(gaddr) : "memory")
#define CP_COMMIT() asm volatile("cp.async.commit_group;" ::: "memory")
#define CP_WAIT(n)  asm volatile("cp.async.wait_group %0;" :: "n"(n) : "memory")

#define MMA_F16(c, a0, a1, a2, a3, b0, b1) \
    asm volatile("mma.sync.aligned.m16n8k16.row.col.f32.f16.f16.f32 " \
                 "{%0,%1,%2,%3}, {%4,%5,%6,%7}, {%8,%9}, {%0,%1,%2,%3};" \
                 : "+f"((c)[0]), "+f"((c)[1]), "+f"((c)[2]), "+f"((c)[3]) \
                 : "r"(a0), "r"(a1), "r"(a2), "r"(a3), "r"(b0), "r"(b1))

#define LDSM4(r0, r1, r2, r3, a) \
    asm volatile("ldmatrix.sync.aligned.m8n8.x4.shared.b16 {%0,%1,%2,%3}, [%4];" \
                 : "=r"(r0), "=r"(r1), "=r"(r2), "=r"(r3) : "r"(a))

#define LDSM4T(r0, r1, r2, r3, a) \
    asm volatile("ldmatrix.sync.aligned.m8n8.x4.trans.shared.b16 {%0,%1,%2,%3}, [%4];" \
                 : "=r"(r0), "=r"(r1), "=r"(r2), "=r"(r3) : "r"(a))

// (1/sqrt(128)) * log2(e) folded into Q
#define QSCALE (0.08838834764831845f * 1.4426950408889634f)

// ---------------------------------------------------------------------------
// fused fp32 -> fp16 conversion, 16 elems/thread (2 independent 16B streams)
// act: 2048 blocks; each weight: 1024 blocks. 4096 elems per block.
// ---------------------------------------------------------------------------
__global__ __launch_bounds__(256)
void cvt_f16_all(const float* __restrict__ act,
                 const float* __restrict__ wq, const float* __restrict__ wk,
                 const float* __restrict__ wv, const float* __restrict__ wo) {
    int blk = blockIdx.x;
    const float* src;
    __half* dst;
    size_t base;
    if (blk < 2048) {
        src = act; dst = g_acth; base = (size_t)blk * 4096;
    } else {
        int wb = blk - 2048;
        int w = wb >> 10;
        int bb = wb & 1023;
        base = (size_t)bb * 4096;
        if (w == 0)      { src = wq; dst = g_wqh; }
        else if (w == 1) { src = wk; dst = g_wkh; }
        else if (w == 2) { src = wv; dst = g_wvh; }
        else             { src = wo; dst = g_woh; }
    }
    // two independent 8-elem streams, 2048 apart (within block's 4096 range)
    size_t i0 = base + (size_t)threadIdx.x * 8;
    size_t i1 = i0 + 2048;
    float4 a0 = *(const float4*)(src + i0);
    float4 a1 = *(const float4*)(src + i0 + 4);
    float4 b0 = *(const float4*)(src + i1);
    float4 b1 = *(const float4*)(src + i1 + 4);
    uint4 oa, ob;
    oa.x = h2u(__floats2half2_rn(a0.x, a0.y));
    oa.y = h2u(__floats2half2_rn(a0.z, a0.w));
    oa.z = h2u(__floats2half2_rn(a1.x, a1.y));
    oa.w = h2u(__floats2half2_rn(a1.z, a1.w));
    ob.x = h2u(__floats2half2_rn(b0.x, b0.y));
    ob.y = h2u(__floats2half2_rn(b0.z, b0.w));
    ob.z = h2u(__floats2half2_rn(b1.x, b1.y));
    ob.w = h2u(__floats2half2_rn(b1.z, b1.w));
    *(uint4*)(dst + i0) = oa;
    *(uint4*)(dst + i1) = ob;
}

// ---------------------------------------------------------------------------
// fp16 mma.sync GEMM (NT): CTA 128x128, 4 warps (2x2), warp tile 64x64.
// BKH=64 (NK=32), 2-stage cp.async pipeline -> 3 CTAs/SM (6 warps... 3/SMSP).
// Single-buffered fragments (register budget 170 @ launch_bounds(128,3)).
// MODE 0: fp32 C;  1: fp16 C;  2: xpos-Q fp16;  3: xpos-K fp16.
// ---------------------------------------------------------------------------
#define BM 128
#define BN 128
#define BKH 64
#define SROW 36                          // u32 per row: 32 data + 4 pad
#define TILE_U (128 * SROW)              // 4608 u32 = 18432 B
#define STAGE_U (2 * TILE_U)
#define STAGE_B (STAGE_U * 4)            // 36864 B
#define GM_STAGES 2
#define GM_SMEM (GM_STAGES * STAGE_B)    // 73728 B
#define NK (EMB / BKH)                   // 32
#define GM_THREADS 128

template<int MODE>
__device__ __forceinline__
void gemm_body(const __half* __restrict__ A, const __half* __restrict__ B,
               void* __restrict__ Cv, uint32_t* smu) {
    const uint32_t sb = smem_u32(smu);
    const int tid = threadIdx.x;
    const int wid = tid >> 5;
    const int lane = tid & 31;
    const int gid = lane >> 2;
    const int tig = lane & 3;
    const int wm = wid >> 1;        // 0..1
    const int wn = wid & 1;         // 0..1
    const int bm = blockIdx.y * BM;
    const int bn = blockIdx.x * BN;

    // ldmatrix per-lane offsets (u32 index into tile)
    const int l7 = lane & 7;
    const int rA = ((lane >> 3) & 1) * 8;
    const int kA = ((lane >> 4) & 1) * 4;
    const int rB = ((lane >> 4) & 1) * 8;
    const int kB = ((lane >> 3) & 1) * 4;
    int aoff[4], boff[4];
#pragma unroll
    for (int mi = 0; mi < 4; mi++)
        aoff[mi] = (wm * 64 + mi * 16 + l7 + rA) * SROW + kA;
#pragma unroll
    for (int p = 0; p < 4; p++)
        boff[p] = (wn * 64 + p * 16 + l7 + rB) * SROW + kB;

    float acc[4][8][4];
#pragma unroll
    for (int mi = 0; mi < 4; mi++)
#pragma unroll
        for (int ni = 0; ni < 8; ni++)
#pragma unroll
            for (int q = 0; q < 4; q++) acc[mi][ni][q] = 0.0f;

    auto issue_stage = [&](int kt, int stage) {
        const uint32_t sbase = sb + stage * STAGE_B;
#pragma unroll
        for (int c = 0; c < 8; c++) {
            int id = tid + c * GM_THREADS;  // 0..1023
            int row = id >> 3;              // 0..127
            int cg = id & 7;                // 0..7
            uint32_t soff = (uint32_t)(row * SROW + cg * 4) * 4u;
            CP_ASYNC16(sbase + soff,
                       A + (size_t)(bm + row) * EMB + kt * BKH + cg * 8);
            CP_ASYNC16_CG(sbase + TILE_U * 4 + soff,
                          B + (size_t)(bn + row) * EMB + kt * BKH + cg * 8);
        }
        CP_COMMIT();
    };

    issue_stage(0, 0);

    for (int kt = 0; kt < NK; kt++) {
        const int s = kt & 1;
        CP_WAIT(0);            // stage kt fully landed (fill overlapped kt-1)
        __syncthreads();       // all warps done reading stage kt-1's buffer
        if (kt + 1 < NK) issue_stage(kt + 1, s ^ 1);

        const uint32_t aB = sb + s * STAGE_B;
        const uint32_t bB = aB + TILE_U * 4;

#pragma unroll
        for (int ks = 0; ks < 4; ks++) {
            const int k0 = ks * 8;
            uint32_t a[4][4];
#pragma unroll
            for (int mi = 0; mi < 4; mi++)
                LDSM4(a[mi][0], a[mi][1], a[mi][2], a[mi][3],
                      aB + (uint32_t)(aoff[mi] + k0) * 4u);
            uint32_t bb[4][4];
#pragma unroll
            for (int p = 0; p < 4; p++)
                LDSM4(bb[p][0], bb[p][1], bb[p][2], bb[p][3],
                      bB + (uint32_t)(boff[p] + k0) * 4u);
#pragma unroll
            for (int mi = 0; mi < 4; mi++)
#pragma unroll
                for (int p = 0; p < 4; p++) {
                    MMA_F16(acc[mi][2 * p], a[mi][0], a[mi][1], a[mi][2], a[mi][3],
                            bb[p][0], bb[p][1]);
                    MMA_F16(acc[mi][2 * p + 1], a[mi][0], a[mi][1], a[mi][2], a[mi][3],
                            bb[p][2], bb[p][3]);
                }
        }
    }

    // epilogue
#pragma unroll
    for (int mi = 0; mi < 4; mi++) {
        const int r0 = bm + wm * 64 + mi * 16 + gid;
        const int r1 = r0 + 8;
#pragma unroll
        for (int ni = 0; ni < 8; ni++) {
            const int c0 = bn + wn * 64 + ni * 8 + tig * 2;
            if (MODE == 0) {
                float* C = (float*)Cv;
                float2 w0; w0.x = acc[mi][ni][0]; w0.y = acc[mi][ni][1];
                float2 w1; w1.x = acc[mi][ni][2]; w1.y = acc[mi][ni][3];
                *(float2*)(C + (size_t)r0 * EMB + c0) = w0;
                *(float2*)(C + (size_t)r1 * EMB + c0) = w1;
            } else if (MODE == 1) {
                __half* C = (__half*)Cv;
                *(uint32_t*)(C + (size_t)r0 * EMB + c0) =
                    h2u(__floats2half2_rn(acc[mi][ni][0], acc[mi][ni][1]));
                *(uint32_t*)(C + (size_t)r1 * EMB + c0) =
                    h2u(__floats2half2_rn(acc[mi][ni][2], acc[mi][ni][3]));
            } else {
                // xpos rotary fused: col pair (c0, c0+1), dr = (c0&127)+2
                __half* C = (__half*)Cv;
                float dr = (float)((c0 & 127) + 2);
                float theta = ex2(-0.1038102531f * dr);           // (1e-4)^(dr/128)
                float lz = __log2f((dr * 0.015625f + 51.2f) * (1.0f / 52.2f));
                float seq0 = (float)((r0 & (SEQ - 1)) - 1024) * (1.0f / 512.0f);
                float seq1 = (float)((r1 & (SEQ - 1)) - 1024) * (1.0f / 512.0f);
                float c0f = __cosf(seq0 * theta), s0f = __sinf(seq0 * theta);
                float c1f = __cosf(seq1 * theta), s1f = __sinf(seq1 * theta);
                float t0, t1;
                if (MODE == 2) { t0 = ex2(seq0 * lz) * QSCALE; t1 = ex2(seq1 * lz) * QSCALE; }
                else           { t0 = ex2(-seq0 * lz);         t1 = ex2(-seq1 * lz); }
                float x0 = acc[mi][ni][0], y0 = acc[mi][ni][1];
                float x1 = acc[mi][ni][2], y1 = acc[mi][ni][3];
                float ox0 = (x0 * c0f - y0 * s0f) * t0;
                float oy0 = (y0 * c0f + x0 * s0f) * t0;
                float ox1 = (x1 * c1f - y1 * s1f) * t1;
                float oy1 = (y1 * c1f + x1 * s1f) * t1;
                *(uint32_t*)(C + (size_t)r0 * EMB + c0) = h2u(__floats2half2_rn(ox0, oy0));
                *(uint32_t*)(C + (size_t)r1 * EMB + c0) = h2u(__floats2half2_rn(ox1, oy1));
            }
        }
    }
}

__global__ __launch_bounds__(GM_THREADS, 3)
void gemm_out(const __half* __restrict__ A, const __half* __restrict__ B,
              float* __restrict__ C) {
    extern __shared__ uint32_t smu[];
    gemm_body<0>(A, B, (void*)C, smu);
}

// Q, K, V GEMMs merged into one launch via blockIdx.z
__global__ __launch_bounds__(GM_THREADS, 3)
void gemm_qkv(const __half* __restrict__ A,
              const __half* __restrict__ Bq, const __half* __restrict__ Bk,
              const __half* __restrict__ Bv,
              __half* __restrict__ Cq, __half* __restrict__ Ck,
              __half* __restrict__ Cv) {
    extern __shared__ uint32_t smu[];
    if (blockIdx.z == 0)      gemm_body<2>(A, Bq, (void*)Cq, smu);
    else if (blockIdx.z == 1) gemm_body<3>(A, Bk, (void*)Ck, smu);
    else                      gemm_body<1>(A, Bv, (void*)Cv, smu);
}

// ---------------------------------------------------------------------------
// FlashAttention-2 causal attention: 2-stage double-buffered K/V pipeline.
// K fragments via ldmatrix; V fragments via ldmatrix.trans from row-major V.
// CTA = 128 threads (4 warps), 64 q rows. K/V tiles [64][136 halves]/stage.
// (unchanged from R15)
// ---------------------------------------------------------------------------
#define AT_KSTG 17408                     // 64*136*2
#define AT_STG  (2 * AT_KSTG)             // 34816 (K + V)
#define AT_SMEM (2 * AT_STG)              // 69632

__global__ __launch_bounds__(128, 2)
void attn_kernel() {
    extern __shared__ __half atsm[];
    const uint32_t sb = smem_u32(atsm);

    const int bid = blockIdx.x;
    const int bh = bid & 31;
    const int qt = 31 - (bid >> 5);   // longest first
    const int b = bh >> 4;
    const int h = bh & 15;
    const int q0 = qt * 64;

    const int tid = threadIdx.x;
    const int wid = tid >> 5;
    const int lane = tid & 31;
    const int gid = lane >> 2;
    const int tig = lane & 3;
    const int l7 = lane & 7;
    const int rB = ((lane >> 4) & 1) * 8;
    const int kB = ((lane >> 3) & 1) * 4;

    const int row0 = q0 + wid * 16 + gid;
    const int row1 = row0 + 8;

    int koff[4];
#pragma unroll
    for (int p = 0; p < 4; p++) koff[p] = (p * 16 + l7 + rB) * 68 + kB;
    const int vrow_l = lane & 15;
    const int vcol_l = ((lane >> 4) & 1) * 8;
    int voff[8];
#pragma unroll
    for (int p = 0; p < 8; p++)
        voff[p] = (vrow_l * 136 + p * 16 + vcol_l) * 2;

    uint32_t aQ[8][4];
    {
        const __half* q0p = g_qh + ((size_t)b * SEQ + row0) * EMB + h * HDIM;
        const __half* q1p = q0p + 8 * EMB;
#pragma unroll
        for (int t = 0; t < 8; t++) {
            aQ[t][0] = *(const uint32_t*)(q0p + t * 16 + 2 * tig);
            aQ[t][1] = *(const uint32_t*)(q1p + t * 16 + 2 * tig);
            aQ[t][2] = *(const uint32_t*)(q0p + t * 16 + 8 + 2 * tig);
            aQ[t][3] = *(const uint32_t*)(q1p + t * 16 + 8 + 2 * tig);
        }
    }

    float O[16][4];
#pragma unroll
    for (int n = 0; n < 16; n++) { O[n][0] = O[n][1] = O[n][2] = O[n][3] = 0.f; }
    float m0 = -1e30f, m1 = -1e30f, l0 = 0.f, l1 = 0.f;

    const __half* kg = g_kh + (size_t)b * SEQ * EMB + h * HDIM;
    const __half* vg = g_vh + (size_t)b * SEQ * EMB + h * HDIM;

    auto issue_kv = [&](int kt, int s) {
        const uint32_t kb_ = sb + s * AT_STG;
        const uint32_t vb_ = kb_ + AT_KSTG;
#pragma unroll
        for (int i = 0; i < 8; i++) {
            int id = tid + i * 128;
            int row = id >> 4, ch = id & 15;
            uint32_t soff = (uint32_t)(row * 136 + ch * 8) * 2;
            size_t goff = (size_t)(kt * 64 + row) * EMB + ch * 8;
            CP_ASYNC16(kb_ + soff, kg + goff);
            CP_ASYNC16(vb_ + soff, vg + goff);
        }
        CP_COMMIT();
    };

    issue_kv(0, 0);

    for (int kt = 0; kt <= qt; kt++) {
        const int s = kt & 1;
        if (kt + 1 <= qt) { issue_kv(kt + 1, s ^ 1); CP_WAIT(1); }
        else              { CP_WAIT(0); }
        __syncthreads();

        const uint32_t kcur = sb + s * AT_STG;
        const uint32_t vcur = kcur + AT_KSTG;

        float sc[8][4];
#pragma unroll
        for (int n = 0; n < 8; n++) sc[n][0] = sc[n][1] = sc[n][2] = sc[n][3] = 0.f;
#pragma unroll
        for (int t = 0; t < 8; t++) {
            const int k0 = t * 8;
            uint32_t kb[4][4];
#pragma unroll
            for (int p = 0; p < 4; p++)
                LDSM4(kb[p][0], kb[p][1], kb[p][2], kb[p][3],
                      kcur + (uint32_t)(koff[p] + k0) * 4u);
#pragma unroll
            for (int p = 0; p < 4; p++) {
                MMA_F16(sc[2 * p], aQ[t][0], aQ[t][1], aQ[t][2], aQ[t][3],
                        kb[p][0], kb[p][1]);
                MMA_F16(sc[2 * p + 1], aQ[t][0], aQ[t][1], aQ[t][2], aQ[t][3],
                        kb[p][2], kb[p][3]);
            }
        }

        if (kt == qt) {
#pragma unroll
            for (int n = 0; n < 8; n++) {
                int col = kt * 64 + n * 8 + 2 * tig;
                if (col > row0)     sc[n][0] = -1e30f;
                if (col + 1 > row0) sc[n][1] = -1e30f;
                if (col > row1)     sc[n][2] = -1e30f;
                if (col + 1 > row1) sc[n][3] = -1e30f;
            }
        }

        float rm0 = -1e30f, rm1 = -1e30f;
#pragma unroll
        for (int n = 0; n < 8; n++) {
            rm0 = fmaxf(rm0, fmaxf(sc[n][0], sc[n][1]));
            rm1 = fmaxf(rm1, fmaxf(sc[n][2], sc[n][3]));
        }
        rm0 = fmaxf(rm0, __shfl_xor_sync(0xffffffffu, rm0, 1));
        rm0 = fmaxf(rm0, __shfl_xor_sync(0xffffffffu, rm0, 2));
        rm1 = fmaxf(rm1, __shfl_xor_sync(0xffffffffu, rm1, 1));
        rm1 = fmaxf(rm1, __shfl_xor_sync(0xffffffffu, rm1, 2));
        float mn0 = fmaxf(m0, rm0), mn1 = fmaxf(m1, rm1);
        float cf0 = ex2(m0 - mn0), cf1 = ex2(m1 - mn1);
        m0 = mn0; m1 = mn1;

        float rs0 = 0.f, rs1 = 0.f;
        uint32_t aP[4][4];
#pragma unroll
        for (int t = 0; t < 4; t++) {
            float p00 = ex2(sc[2 * t][0] - mn0),     p01 = ex2(sc[2 * t][1] - mn0);
            float p02 = ex2(sc[2 * t][2] - mn1),     p03 = ex2(sc[2 * t][3] - mn1);
            float p10 = ex2(sc[2 * t + 1][0] - mn0), p11 = ex2(sc[2 * t + 1][1] - mn0);
            float p12 = ex2(sc[2 * t + 1][2] - mn1), p13 = ex2(sc[2 * t + 1][3] - mn1);
            rs0 += (p00 + p01) + (p10 + p11);
            rs1 += (p02 + p03) + (p12 + p13);
            aP[t][0] = h2u(__floats2half2_rn(p00, p01));
            aP[t][1] = h2u(__floats2half2_rn(p02, p03));
            aP[t][2] = h2u(__floats2half2_rn(p10, p11));
            aP[t][3] = h2u(__floats2half2_rn(p12, p13));
        }
        l0 = l0 * cf0 + rs0;
        l1 = l1 * cf1 + rs1;

#pragma unroll
        for (int n = 0; n < 16; n++) {
            O[n][0] *= cf0; O[n][1] *= cf0; O[n][2] *= cf1; O[n][3] *= cf1;
        }

#pragma unroll
        for (int t = 0; t < 4; t++) {
            const uint32_t vt_base = vcur + (uint32_t)(t * 16 * 136 * 2);
#pragma unroll
            for (int p = 0; p < 8; p++) {
                uint32_t v0, v1, v2, v3;
                LDSM4T(v0, v1, v2, v3, vt_base + (uint32_t)voff[p]);
                MMA_F16(O[2 * p], aP[t][0], aP[t][1], aP[t][2], aP[t][3], v0, v1);
                MMA_F16(O[2 * p + 1], aP[t][0], aP[t][1], aP[t][2], aP[t][3], v2, v3);
            }
        }
        __syncthreads();
    }

    l0 += __shfl_xor_sync(0xffffffffu, l0, 1);
    l0 += __shfl_xor_sync(0xffffffffu, l0, 2);
    l1 += __shfl_xor_sync(0xffffffffu, l1, 1);
    l1 += __shfl_xor_sync(0xffffffffu, l1, 2);
    float inv0 = 1.0f / l0, inv1 = 1.0f / l1;

    __half* o0 = g_atth + ((size_t)b * SEQ + row0) * EMB + h * HDIM;
    __half* o1 = o0 + 8 * EMB;
#pragma unroll
    for (int n = 0; n < 16; n++) {
        *(uint32_t*)(o0 + n * 8 + 2 * tig) =
            h2u(__floats2half2_rn(O[n][0] * inv0, O[n][1] * inv0));
        *(uint32_t*)(o1 + n * 8 + 2 * tig) =
            h2u(__floats2half2_rn(O[n][2] * inv1, O[n][3] * inv1));
    }
}

// ---------------------------------------------------------------------------
// Launch
// ---------------------------------------------------------------------------
extern "C" void kernel_launch(void* const* d_in, const int* in_sizes, int n_in,
                              void* d_out, int out_size) {
    const float* act = (const float*)d_in[0];
    const float* Wq  = (const float*)d_in[1];
    const float* Wk  = (const float*)d_in[2];
    const float* Wv  = (const float*)d_in[3];
    const float* Wo  = (const float*)d_in[4];
    float* out = (float*)d_out;

    __half *acth, *atth, *qh, *kh, *vh, *wqh, *wkh, *wvh, *woh;
    cudaGetSymbolAddress((void**)&acth, g_acth);
    cudaGetSymbolAddress((void**)&atth, g_atth);
    cudaGetSymbolAddress((void**)&qh, g_qh);
    cudaGetSymbolAddress((void**)&kh, g_kh);
    cudaGetSymbolAddress((void**)&vh, g_vh);
    cudaGetSymbolAddress((void**)&wqh, g_wqh);
    cudaGetSymbolAddress((void**)&wkh, g_wkh);
    cudaGetSymbolAddress((void**)&wvh, g_wvh);
    cudaGetSymbolAddress((void**)&woh, g_woh);

    cudaFuncSetAttribute(gemm_out, cudaFuncAttributeMaxDynamicSharedMemorySize, GM_SMEM);
    cudaFuncSetAttribute(gemm_qkv, cudaFuncAttributeMaxDynamicSharedMemorySize, GM_SMEM);
    cudaFuncSetAttribute(attn_kernel, cudaFuncAttributeMaxDynamicSharedMemorySize, AT_SMEM);

    dim3 ggrid(EMB / BN, BATCH * SEQ / BM);          // (16, 32)
    dim3 qkvgrid(EMB / BN, BATCH * SEQ / BM, 3);     // (16, 32, 3)

    // 1: conversions (16 elems/thread, 2 streams)
    cvt_f16_all<<<2048 + 4 * 1024, 256>>>(act, Wq, Wk, Wv, Wo);
    // 2: Q, K, V GEMMs (one launch; xpos fused into Q/K epilogues)
    gemm_qkv<<<qkvgrid, GM_THREADS, GM_SMEM>>>(acth, wqh, wkh, wvh, qh, kh, vh);
    // 3: attention (V consumed row-major via ldmatrix.trans)
    attn_kernel<<<1024, 128, AT_SMEM>>>();
    // 4: output GEMM
    gemm_out<<<ggrid, GM_THREADS, GM_SMEM>>>(atth, woh, out);
}

// round 17
// speedup vs baseline: 1.0616x; 1.0616x over previous
#include <cuda_runtime.h>
#include <cuda_fp16.h>
#include <math.h>
#include <stdint.h>

// Problem constants
#define BATCH 2
#define SEQ   2048
#define EMB   2048
#define HEADS 16
#define HDIM  128

// Scratch buffers (allocation-free rule: __device__ globals)
__device__ __half g_acth[BATCH * SEQ * EMB];  // fp16 activations
__device__ __half g_atth[BATCH * SEQ * EMB];  // fp16 attention output
__device__ __half g_qh[BATCH * SEQ * EMB];    // fp16 rotated+scaled Q
__device__ __half g_kh[BATCH * SEQ * EMB];    // fp16 rotated K
__device__ __half g_vh[BATCH * SEQ * EMB];    // fp16 V (row-major)
__device__ __half g_wqh[EMB * EMB];
__device__ __half g_wkh[EMB * EMB];
__device__ __half g_wvh[EMB * EMB];
__device__ __half g_woh[EMB * EMB];

// ---------------------------------------------------------------------------
// helpers
// ---------------------------------------------------------------------------
__device__ __forceinline__ uint32_t smem_u32(const void* p) {
    uint32_t a;
    asm("{ .reg .u64 t; cvta.to.shared.u64 t, %1; cvt.u32.u64 %0, t; }"
        : "=r"(a) : "l"(p));
    return a;
}

__device__ __forceinline__ float ex2(float x) {
    float r;
    asm("ex2.approx.ftz.f32 %0, %1;" : "=f"(r) : "f"(x));
    return r;
}

__device__ __forceinline__ uint32_t h2u(__half2 h) {
    return *reinterpret_cast<uint32_t*>(&h);
}

#define CP_ASYNC16(saddr, gaddr) \
    asm volatile("cp.async.ca.shared.global [%0], [%1], 16;" \
                 :: "r"(saddr), "l"(gaddr) : "memory")
#define CP_ASYNC16_CG(saddr, gaddr) \
    asm volatile("cp.async.cg.shared.global [%0], [%1], 16;" \
                 :: "r"(saddr), "l"(gaddr) : "memory")
#define CP_COMMIT() asm volatile("cp.async.commit_group;" ::: "memory")
#define CP_WAIT(n)  asm volatile("cp.async.wait_group %0;" :: "n"(n) : "memory")

#define MMA_F16(c, a0, a1, a2, a3, b0, b1) \
    asm volatile("mma.sync.aligned.m16n8k16.row.col.f32.f16.f16.f32 " \
                 "{%0,%1,%2,%3}, {%4,%5,%6,%7}, {%8,%9}, {%0,%1,%2,%3};" \
                 : "+f"((c)[0]), "+f"((c)[1]), "+f"((c)[2]), "+f"((c)[3]) \
                 : "r"(a0), "r"(a1), "r"(a2), "r"(a3), "r"(b0), "r"(b1))

#define LDSM4(r0, r1, r2, r3, a) \
    asm volatile("ldmatrix.sync.aligned.m8n8.x4.shared.b16 {%0,%1,%2,%3}, [%4];" \
                 : "=r"(r0), "=r"(r1), "=r"(r2), "=r"(r3) : "r"(a))

#define LDSM4T(r0, r1, r2, r3, a) \
    asm volatile("ldmatrix.sync.aligned.m8n8.x4.trans.shared.b16 {%0,%1,%2,%3}, [%4];" \
                 : "=r"(r0), "=r"(r1), "=r"(r2), "=r"(r3) : "r"(a))

// (1/sqrt(128)) * log2(e) folded into Q
#define QSCALE (0.08838834764831845f * 1.4426950408889634f)

// ---------------------------------------------------------------------------
// fused fp32 -> fp16 conversion, 16 elems/thread (2 independent 16B streams)
// ---------------------------------------------------------------------------
__global__ __launch_bounds__(256)
void cvt_f16_all(const float* __restrict__ act,
                 const float* __restrict__ wq, const float* __restrict__ wk,
                 const float* __restrict__ wv, const float* __restrict__ wo) {
    int blk = blockIdx.x;
    const float* src;
    __half* dst;
    size_t base;
    if (blk < 2048) {
        src = act; dst = g_acth; base = (size_t)blk * 4096;
    } else {
        int wb = blk - 2048;
        int w = wb >> 10;
        int bb = wb & 1023;
        base = (size_t)bb * 4096;
        if (w == 0)      { src = wq; dst = g_wqh; }
        else if (w == 1) { src = wk; dst = g_wkh; }
        else if (w == 2) { src = wv; dst = g_wvh; }
        else             { src = wo; dst = g_woh; }
    }
    size_t i0 = base + (size_t)threadIdx.x * 8;
    size_t i1 = i0 + 2048;
    float4 a0 = *(const float4*)(src + i0);
    float4 a1 = *(const float4*)(src + i0 + 4);
    float4 b0 = *(const float4*)(src + i1);
    float4 b1 = *(const float4*)(src + i1 + 4);
    uint4 oa, ob;
    oa.x = h2u(__floats2half2_rn(a0.x, a0.y));
    oa.y = h2u(__floats2half2_rn(a0.z, a0.w));
    oa.z = h2u(__floats2half2_rn(a1.x, a1.y));
    oa.w = h2u(__floats2half2_rn(a1.z, a1.w));
    ob.x = h2u(__floats2half2_rn(b0.x, b0.y));
    ob.y = h2u(__floats2half2_rn(b0.z, b0.w));
    ob.z = h2u(__floats2half2_rn(b1.x, b1.y));
    ob.w = h2u(__floats2half2_rn(b1.z, b1.w));
    *(uint4*)(dst + i0) = oa;
    *(uint4*)(dst + i1) = ob;
}

// ---------------------------------------------------------------------------
// fp16 mma.sync GEMM (NT): CTA 128x128, 4 warps (2x2), warp tile 64x64.
// BKH=64 (NK=32), 3-stage cp.async pipeline, ldmatrix fragment loads with
// explicit cross-ks fragment double-buffering. (R15 champion config.)
// MODE 0: fp32 C;  1: fp16 C;  2: xpos-Q fp16;  3: xpos-K fp16.
// ---------------------------------------------------------------------------
#define BM 128
#define BN 128
#define BKH 64
#define SROW 36                          // u32 per row: 32 data + 4 pad
#define TILE_U (128 * SROW)              // 4608 u32 = 18432 B
#define STAGE_U (2 * TILE_U)
#define STAGE_B (STAGE_U * 4)            // 36864 B
#define GM_STAGES 3
#define GM_SMEM (GM_STAGES * STAGE_B)    // 110592 B
#define NK (EMB / BKH)                   // 32
#define GM_THREADS 128

template<int MODE>
__device__ __forceinline__
void gemm_body(const __half* __restrict__ A, const __half* __restrict__ B,
               void* __restrict__ Cv, uint32_t* smu) {
    const uint32_t sb = smem_u32(smu);
    const int tid = threadIdx.x;
    const int wid = tid >> 5;
    const int lane = tid & 31;
    const int gid = lane >> 2;
    const int tig = lane & 3;
    const int wm = wid >> 1;        // 0..1
    const int wn = wid & 1;         // 0..1
    const int bm = blockIdx.y * BM;
    const int bn = blockIdx.x * BN;

    // ldmatrix per-lane offsets (u32 index into tile)
    const int l7 = lane & 7;
    const int rA = ((lane >> 3) & 1) * 8;
    const int kA = ((lane >> 4) & 1) * 4;
    const int rB = ((lane >> 4) & 1) * 8;
    const int kB = ((lane >> 3) & 1) * 4;
    int aoff[4], boff[4];
#pragma unroll
    for (int mi = 0; mi < 4; mi++)
        aoff[mi] = (wm * 64 + mi * 16 + l7 + rA) * SROW + kA;
#pragma unroll
    for (int p = 0; p < 4; p++)
        boff[p] = (wn * 64 + p * 16 + l7 + rB) * SROW + kB;

    float acc[4][8][4];
#pragma unroll
    for (int mi = 0; mi < 4; mi++)
#pragma unroll
        for (int ni = 0; ni < 8; ni++)
#pragma unroll
            for (int q = 0; q < 4; q++) acc[mi][ni][q] = 0.0f;

    auto issue_stage = [&](int kt, int stage) {
        const uint32_t sbase = sb + stage * STAGE_B;
#pragma unroll
        for (int c = 0; c < 8; c++) {
            int id = tid + c * GM_THREADS;  // 0..1023
            int row = id >> 3;              // 0..127
            int cg = id & 7;                // 0..7
            uint32_t soff = (uint32_t)(row * SROW + cg * 4) * 4u;
            CP_ASYNC16(sbase + soff,
                       A + (size_t)(bm + row) * EMB + kt * BKH + cg * 8);
            CP_ASYNC16_CG(sbase + TILE_U * 4 + soff,
                          B + (size_t)(bn + row) * EMB + kt * BKH + cg * 8);
        }
        CP_COMMIT();
    };

    issue_stage(0, 0);
    issue_stage(1, 1);

    // double-buffered fragments across ks
    uint32_t af[2][4][4], bf[2][4][4];

    for (int kt = 0; kt < NK; kt++) {
        const int s = kt % 3;
        if (kt + 1 < NK) { CP_WAIT(1); } else { CP_WAIT(0); }
        __syncthreads();

        const uint32_t aB = sb + s * STAGE_B;
        const uint32_t bB = aB + TILE_U * 4;

        // preload ks=0 fragments
#pragma unroll
        for (int mi = 0; mi < 4; mi++)
            LDSM4(af[0][mi][0], af[0][mi][1], af[0][mi][2], af[0][mi][3],
                  aB + (uint32_t)aoff[mi] * 4u);
#pragma unroll
        for (int p = 0; p < 4; p++)
            LDSM4(bf[0][p][0], bf[0][p][1], bf[0][p][2], bf[0][p][3],
                  bB + (uint32_t)boff[p] * 4u);

#pragma unroll
        for (int ks = 0; ks < 4; ks++) {
            const int cur = ks & 1;
            const int nxt = cur ^ 1;
            // prefetch next ks fragments before issuing current MMAs
            if (ks < 3) {
                const int k0 = (ks + 1) * 8;
#pragma unroll
                for (int mi = 0; mi < 4; mi++)
                    LDSM4(af[nxt][mi][0], af[nxt][mi][1], af[nxt][mi][2], af[nxt][mi][3],
                          aB + (uint32_t)(aoff[mi] + k0) * 4u);
#pragma unroll
                for (int p = 0; p < 4; p++)
                    LDSM4(bf[nxt][p][0], bf[nxt][p][1], bf[nxt][p][2], bf[nxt][p][3],
                          bB + (uint32_t)(boff[p] + k0) * 4u);
            }
#pragma unroll
            for (int mi = 0; mi < 4; mi++)
#pragma unroll
                for (int p = 0; p < 4; p++) {
                    MMA_F16(acc[mi][2 * p], af[cur][mi][0], af[cur][mi][1],
                            af[cur][mi][2], af[cur][mi][3],
                            bf[cur][p][0], bf[cur][p][1]);
                    MMA_F16(acc[mi][2 * p + 1], af[cur][mi][0], af[cur][mi][1],
                            af[cur][mi][2], af[cur][mi][3],
                            bf[cur][p][2], bf[cur][p][3]);
                }
            if (ks == 0 && kt + 2 < NK) issue_stage(kt + 2, (kt + 2) % 3);
        }
    }

    // epilogue
#pragma unroll
    for (int mi = 0; mi < 4; mi++) {
        const int r0 = bm + wm * 64 + mi * 16 + gid;
        const int r1 = r0 + 8;
#pragma unroll
        for (int ni = 0; ni < 8; ni++) {
            const int c0 = bn + wn * 64 + ni * 8 + tig * 2;
            if (MODE == 0) {
                float* C = (float*)Cv;
                float2 w0; w0.x = acc[mi][ni][0]; w0.y = acc[mi][ni][1];
                float2 w1; w1.x = acc[mi][ni][2]; w1.y = acc[mi][ni][3];
                *(float2*)(C + (size_t)r0 * EMB + c0) = w0;
                *(float2*)(C + (size_t)r1 * EMB + c0) = w1;
            } else if (MODE == 1) {
                __half* C = (__half*)Cv;
                *(uint32_t*)(C + (size_t)r0 * EMB + c0) =
                    h2u(__floats2half2_rn(acc[mi][ni][0], acc[mi][ni][1]));
                *(uint32_t*)(C + (size_t)r1 * EMB + c0) =
                    h2u(__floats2half2_rn(acc[mi][ni][2], acc[mi][ni][3]));
            } else {
                // xpos rotary fused: col pair (c0, c0+1), dr = (c0&127)+2
                __half* C = (__half*)Cv;
                float dr = (float)((c0 & 127) + 2);
                float theta = ex2(-0.1038102531f * dr);           // (1e-4)^(dr/128)
                float lz = __log2f((dr * 0.015625f + 51.2f) * (1.0f / 52.2f));
                float seq0 = (float)((r0 & (SEQ - 1)) - 1024) * (1.0f / 512.0f);
                float seq1 = (float)((r1 & (SEQ - 1)) - 1024) * (1.0f / 512.0f);
                float c0f = __cosf(seq0 * theta), s0f = __sinf(seq0 * theta);
                float c1f = __cosf(seq1 * theta), s1f = __sinf(seq1 * theta);
                float t0, t1;
                if (MODE == 2) { t0 = ex2(seq0 * lz) * QSCALE; t1 = ex2(seq1 * lz) * QSCALE; }
                else           { t0 = ex2(-seq0 * lz);         t1 = ex2(-seq1 * lz); }
                float x0 = acc[mi][ni][0], y0 = acc[mi][ni][1];
                float x1 = acc[mi][ni][2], y1 = acc[mi][ni][3];
                float ox0 = (x0 * c0f - y0 * s0f) * t0;
                float oy0 = (y0 * c0f + x0 * s0f) * t0;
                float ox1 = (x1 * c1f - y1 * s1f) * t1;
                float oy1 = (y1 * c1f + x1 * s1f) * t1;
                *(uint32_t*)(C + (size_t)r0 * EMB + c0) = h2u(__floats2half2_rn(ox0, oy0));
                *(uint32_t*)(C + (size_t)r1 * EMB + c0) = h2u(__floats2half2_rn(ox1, oy1));
            }
        }
    }
}

__global__ __launch_bounds__(GM_THREADS, 2)
void gemm_out(const __half* __restrict__ A, const __half* __restrict__ B,
              float* __restrict__ C) {
    extern __shared__ uint32_t smu[];
    gemm_body<0>(A, B, (void*)C, smu);
}

// Q, K, V GEMMs merged into one launch via blockIdx.z
__global__ __launch_bounds__(GM_THREADS, 2)
void gemm_qkv(const __half* __restrict__ A,
              const __half* __restrict__ Bq, const __half* __restrict__ Bk,
              const __half* __restrict__ Bv,
              __half* __restrict__ Cq, __half* __restrict__ Ck,
              __half* __restrict__ Cv) {
    extern __shared__ uint32_t smu[];
    if (blockIdx.z == 0)      gemm_body<2>(A, Bq, (void*)Cq, smu);
    else if (blockIdx.z == 1) gemm_body<3>(A, Bk, (void*)Ck, smu);
    else                      gemm_body<1>(A, Bv, (void*)Cv, smu);
}

// ---------------------------------------------------------------------------
// FlashAttention-2 causal attention: 2-stage double-buffered K/V pipeline.
// K fragments via ldmatrix; V fragments via ldmatrix.trans from row-major V.
// CTA = 128 threads (4 warps), 64 q rows. K/V tiles [64][136 halves]/stage.
// ---------------------------------------------------------------------------
#define AT_KSTG 17408                     // 64*136*2
#define AT_STG  (2 * AT_KSTG)             // 34816 (K + V)
#define AT_SMEM (2 * AT_STG)              // 69632

__global__ __launch_bounds__(128, 2)
void attn_kernel() {
    extern __shared__ __half atsm[];
    const uint32_t sb = smem_u32(atsm);

    const int bid = blockIdx.x;
    const int bh = bid & 31;
    const int qt = 31 - (bid >> 5);   // longest first
    const int b = bh >> 4;
    const int h = bh & 15;
    const int q0 = qt * 64;

    const int tid = threadIdx.x;
    const int wid = tid >> 5;
    const int lane = tid & 31;
    const int gid = lane >> 2;
    const int tig = lane & 3;
    const int l7 = lane & 7;
    const int rB = ((lane >> 4) & 1) * 8;
    const int kB = ((lane >> 3) & 1) * 4;

    const int row0 = q0 + wid * 16 + gid;
    const int row1 = row0 + 8;

    int koff[4];
#pragma unroll
    for (int p = 0; p < 4; p++) koff[p] = (p * 16 + l7 + rB) * 68 + kB;
    const int vrow_l = lane & 15;
    const int vcol_l = ((lane >> 4) & 1) * 8;
    int voff[8];
#pragma unroll
    for (int p = 0; p < 8; p++)
        voff[p] = (vrow_l * 136 + p * 16 + vcol_l) * 2;

    uint32_t aQ[8][4];
    {
        const __half* q0p = g_qh + ((size_t)b * SEQ + row0) * EMB + h * HDIM;
        const __half* q1p = q0p + 8 * EMB;
#pragma unroll
        for (int t = 0; t < 8; t++) {
            aQ[t][0] = *(const uint32_t*)(q0p + t * 16 + 2 * tig);
            aQ[t][1] = *(const uint32_t*)(q1p + t * 16 + 2 * tig);
            aQ[t][2] = *(const uint32_t*)(q0p + t * 16 + 8 + 2 * tig);
            aQ[t][3] = *(const uint32_t*)(q1p + t * 16 + 8 + 2 * tig);
        }
    }

    float O[16][4];
#pragma unroll
    for (int n = 0; n < 16; n++) { O[n][0] = O[n][1] = O[n][2] = O[n][3] = 0.f; }
    float m0 = -1e30f, m1 = -1e30f, l0 = 0.f, l1 = 0.f;

    const __half* kg = g_kh + (size_t)b * SEQ * EMB + h * HDIM;
    const __half* vg = g_vh + (size_t)b * SEQ * EMB + h * HDIM;

    auto issue_kv = [&](int kt, int s) {
        const uint32_t kb_ = sb + s * AT_STG;
        const uint32_t vb_ = kb_ + AT_KSTG;
#pragma unroll
        for (int i = 0; i < 8; i++) {
            int id = tid + i * 128;
            int row = id >> 4, ch = id & 15;
            uint32_t soff = (uint32_t)(row * 136 + ch * 8) * 2;
            size_t goff = (size_t)(kt * 64 + row) * EMB + ch * 8;
            CP_ASYNC16(kb_ + soff, kg + goff);
            CP_ASYNC16(vb_ + soff, vg + goff);
        }
        CP_COMMIT();
    };

    issue_kv(0, 0);

    for (int kt = 0; kt <= qt; kt++) {
        const int s = kt & 1;
        if (kt + 1 <= qt) { issue_kv(kt + 1, s ^ 1); CP_WAIT(1); }
        else              { CP_WAIT(0); }
        __syncthreads();

        const uint32_t kcur = sb + s * AT_STG;
        const uint32_t vcur = kcur + AT_KSTG;

        float sc[8][4];
#pragma unroll
        for (int n = 0; n < 8; n++) sc[n][0] = sc[n][1] = sc[n][2] = sc[n][3] = 0.f;
#pragma unroll
        for (int t = 0; t < 8; t++) {
            const int k0 = t * 8;
            uint32_t kb[4][4];
#pragma unroll
            for (int p = 0; p < 4; p++)
                LDSM4(kb[p][0], kb[p][1], kb[p][2], kb[p][3],
                      kcur + (uint32_t)(koff[p] + k0) * 4u);
#pragma unroll
            for (int p = 0; p < 4; p++) {
                MMA_F16(sc[2 * p], aQ[t][0], aQ[t][1], aQ[t][2], aQ[t][3],
                        kb[p][0], kb[p][1]);
                MMA_F16(sc[2 * p + 1], aQ[t][0], aQ[t][1], aQ[t][2], aQ[t][3],
                        kb[p][2], kb[p][3]);
            }
        }

        if (kt == qt) {
#pragma unroll
            for (int n = 0; n < 8; n++) {
                int col = kt * 64 + n * 8 + 2 * tig;
                if (col > row0)     sc[n][0] = -1e30f;
                if (col + 1 > row0) sc[n][1] = -1e30f;
                if (col > row1)     sc[n][2] = -1e30f;
                if (col + 1 > row1) sc[n][3] = -1e30f;
            }
        }

        float rm0 = -1e30f, rm1 = -1e30f;
#pragma unroll
        for (int n = 0; n < 8; n++) {
            rm0 = fmaxf(rm0, fmaxf(sc[n][0], sc[n][1]));
            rm1 = fmaxf(rm1, fmaxf(sc[n][2], sc[n][3]));
        }
        rm0 = fmaxf(rm0, __shfl_xor_sync(0xffffffffu, rm0, 1));
        rm0 = fmaxf(rm0, __shfl_xor_sync(0xffffffffu, rm0, 2));
        rm1 = fmaxf(rm1, __shfl_xor_sync(0xffffffffu, rm1, 1));
        rm1 = fmaxf(rm1, __shfl_xor_sync(0xffffffffu, rm1, 2));
        float mn0 = fmaxf(m0, rm0), mn1 = fmaxf(m1, rm1);
        float cf0 = ex2(m0 - mn0), cf1 = ex2(m1 - mn1);
        m0 = mn0; m1 = mn1;

        float rs0 = 0.f, rs1 = 0.f;
        uint32_t aP[4][4];
#pragma unroll
        for (int t = 0; t < 4; t++) {
            float p00 = ex2(sc[2 * t][0] - mn0),     p01 = ex2(sc[2 * t][1] - mn0);
            float p02 = ex2(sc[2 * t][2] - mn1),     p03 = ex2(sc[2 * t][3] - mn1);
            float p10 = ex2(sc[2 * t + 1][0] - mn0), p11 = ex2(sc[2 * t + 1][1] - mn0);
            float p12 = ex2(sc[2 * t + 1][2] - mn1), p13 = ex2(sc[2 * t + 1][3] - mn1);
            rs0 += (p00 + p01) + (p10 + p11);
            rs1 += (p02 + p03) + (p12 + p13);
            aP[t][0] = h2u(__floats2half2_rn(p00, p01));
            aP[t][1] = h2u(__floats2half2_rn(p02, p03));
            aP[t][2] = h2u(__floats2half2_rn(p10, p11));
            aP[t][3] = h2u(__floats2half2_rn(p12, p13));
        }
        l0 = l0 * cf0 + rs0;
        l1 = l1 * cf1 + rs1;

#pragma unroll
        for (int n = 0; n < 16; n++) {
            O[n][0] *= cf0; O[n][1] *= cf0; O[n][2] *= cf1; O[n][3] *= cf1;
        }

#pragma unroll
        for (int t = 0; t < 4; t++) {
            const uint32_t vt_base = vcur + (uint32_t)(t * 16 * 136 * 2);
#pragma unroll
            for (int p = 0; p < 8; p++) {
                uint32_t v0, v1, v2, v3;
                LDSM4T(v0, v1, v2, v3, vt_base + (uint32_t)voff[p]);
                MMA_F16(O[2 * p], aP[t][0], aP[t][1], aP[t][2], aP[t][3], v0, v1);
                MMA_F16(O[2 * p + 1], aP[t][0], aP[t][1], aP[t][2], aP[t][3], v2, v3);
            }
        }
        __syncthreads();
    }

    l0 += __shfl_xor_sync(0xffffffffu, l0, 1);
    l0 += __shfl_xor_sync(0xffffffffu, l0, 2);
    l1 += __shfl_xor_sync(0xffffffffu, l1, 1);
    l1 += __shfl_xor_sync(0xffffffffu, l1, 2);
    float inv0 = 1.0f / l0, inv1 = 1.0f / l1;

    __half* o0 = g_atth + ((size_t)b * SEQ + row0) * EMB + h * HDIM;
    __half* o1 = o0 + 8 * EMB;
#pragma unroll
    for (int n = 0; n < 16; n++) {
        *(uint32_t*)(o0 + n * 8 + 2 * tig) =
            h2u(__floats2half2_rn(O[n][0] * inv0, O[n][1] * inv0));
        *(uint32_t*)(o1 + n * 8 + 2 * tig) =
            h2u(__floats2half2_rn(O[n][2] * inv1, O[n][3] * inv1));
    }
}

// ---------------------------------------------------------------------------
// Launch
// ---------------------------------------------------------------------------
extern "C" void kernel_launch(void* const* d_in, const int* in_sizes, int n_in,
                              void* d_out, int out_size) {
    const float* act = (const float*)d_in[0];
    const float* Wq  = (const float*)d_in[1];
    const float* Wk  = (const float*)d_in[2];
    const float* Wv  = (const float*)d_in[3];
    const float* Wo  = (const float*)d_in[4];
    float* out = (float*)d_out;

    __half *acth, *atth, *qh, *kh, *vh, *wqh, *wkh, *wvh, *woh;
    cudaGetSymbolAddress((void**)&acth, g_acth);
    cudaGetSymbolAddress((void**)&atth, g_atth);
    cudaGetSymbolAddress((void**)&qh, g_qh);
    cudaGetSymbolAddress((void**)&kh, g_kh);
    cudaGetSymbolAddress((void**)&vh, g_vh);
    cudaGetSymbolAddress((void**)&wqh, g_wqh);
    cudaGetSymbolAddress((void**)&wkh, g_wkh);
    cudaGetSymbolAddress((void**)&wvh, g_wvh);
    cudaGetSymbolAddress((void**)&woh, g_woh);

    cudaFuncSetAttribute(gemm_out, cudaFuncAttributeMaxDynamicSharedMemorySize, GM_SMEM);
    cudaFuncSetAttribute(gemm_qkv, cudaFuncAttributeMaxDynamicSharedMemorySize, GM_SMEM);
    cudaFuncSetAttribute(attn_kernel, cudaFuncAttributeMaxDynamicSharedMemorySize, AT_SMEM);

    dim3 ggrid(EMB / BN, BATCH * SEQ / BM);          // (16, 32)
    dim3 qkvgrid(EMB / BN, BATCH * SEQ / BM, 3);     // (16, 32, 3)

    // 1: conversions (16 elems/thread, 2 streams)
    cvt_f16_all<<<2048 + 4 * 1024, 256>>>(act, Wq, Wk, Wv, Wo);
    // 2: Q, K, V GEMMs (one launch; xpos fused into Q/K epilogues)
    gemm_qkv<<<qkvgrid, GM_THREADS, GM_SMEM>>>(acth, wqh, wkh, wvh, qh, kh, vh);
    // 3: attention (V consumed row-major via ldmatrix.trans)
    attn_kernel<<<1024, 128, AT_SMEM>>>();
    // 4: output GEMM
    gemm_out<<<ggrid, GM_THREADS, GM_SMEM>>>(atth, woh, out);
}